// round 1
// baseline (speedup 1.0000x reference)
#include <cuda_runtime.h>
#include <cuda_bf16.h>

// PositionalEncoding: out[p][j] = X[p][j] + (j even ? sin(p*w_j) : cos(p*w_j))
//   w_j = 10000^{-(j + (j%2))/n},  n = 4096, m = 8192 rows.
//
// Strategy: HBM-bound elementwise. Avoid per-element sin/cos by using the
// angle-addition recurrence along the row axis:
//   s_{p+1} = s_p*cos(w) + c_p*sin(w)
//   c_{p+1} = c_p*cos(w) - s_p*sin(w)
// Each thread owns 4 consecutive columns (float4) and ROWS consecutive rows:
// 8 precise sincosf calls amortized over 4*ROWS elements, then 4 FMAs/elem.

#define PE_M     8192
#define PE_N     4096
#define PE_NV4   (PE_N / 4)      // 1024 float4 per row
#define PE_ROWS  64              // rows per thread
#define PE_TPB   128             // threads per block (column-quads)

__global__ __launch_bounds__(PE_TPB)
void pe_kernel(const float4* __restrict__ X, float4* __restrict__ Out) {
    const int cv   = blockIdx.x * PE_TPB + threadIdx.x;  // column-quad index, 0..1023
    const int row0 = blockIdx.y * PE_ROWS;

    // log2(10000)
    const float L2_10K = 13.287712379549449f;

    float s[4], c[4], sw[4], cw[4];
#pragma unroll
    for (int k = 0; k < 4; k++) {
        const int j = 4 * cv + k;
        // exponent e = (j + (j%2)) / n  -- exact in fp32 (int / 2^12)
        const float e = (float)(j + (j & 1)) * (1.0f / (float)PE_N);
        const float w = exp2f(-e * L2_10K);       // 10000^{-e}
        float ss, cc;
        sincosf((float)row0 * w, &ss, &cc);       // precise: angle can reach 8191
        s[k] = ss; c[k] = cc;
        sincosf(w, &ss, &cc);                     // per-row rotation
        sw[k] = ss; cw[k] = cc;
    }

    const float4* __restrict__ xp = X   + (size_t)row0 * PE_NV4 + cv;
    float4*       __restrict__ yp = Out + (size_t)row0 * PE_NV4 + cv;

#pragma unroll 4
    for (int r = 0; r < PE_ROWS; r++) {
        float4 x = *xp;
        float4 y;
        // columns 4cv+{0,1,2,3} -> parity {even, odd, even, odd} -> {sin, cos, sin, cos}
        y.x = x.x + s[0];
        y.y = x.y + c[1];
        y.z = x.z + s[2];
        y.w = x.w + c[3];
        *yp = y;
        xp += PE_NV4;
        yp += PE_NV4;
#pragma unroll
        for (int k = 0; k < 4; k++) {
            const float ns = fmaf(s[k], cw[k],  c[k] * sw[k]);
            const float nc = fmaf(c[k], cw[k], -s[k] * sw[k]);
            s[k] = ns; c[k] = nc;
        }
    }
}

extern "C" void kernel_launch(void* const* d_in, const int* in_sizes, int n_in,
                              void* d_out, int out_size) {
    (void)in_sizes; (void)n_in; (void)out_size;
    const float4* X   = (const float4*)d_in[0];
    float4*       Out = (float4*)d_out;

    dim3 block(PE_TPB);
    dim3 grid(PE_NV4 / PE_TPB, PE_M / PE_ROWS);   // (8, 128) = 1024 CTAs
    pe_kernel<<<grid, block>>>(X, Out);
}

// round 2
// speedup vs baseline: 1.1053x; 1.1053x over previous
#include <cuda_runtime.h>
#include <cuda_bf16.h>

// PositionalEncoding: out[p][j] = X[p][j] + (j even ? sin(p*w_j) : cos(p*w_j))
//   w_j = 10000^{-(j + (j%2))/n},  n = 4096, m = 8192 rows.
//
// R2: same angle-addition recurrence, but occupancy-tuned:
//   TPB=256 (8 warps/CTA), ROWS=32, 1024 CTAs -> 8 CTAs/SM, 64 warps (100% occ)
//   to supply enough outstanding LDG.128 to saturate HBM.

#define PE_M     8192
#define PE_N     4096
#define PE_NV4   (PE_N / 4)      // 1024 float4 per row
#define PE_ROWS  32              // rows per thread
#define PE_TPB   256             // threads per block (column-quads)

__global__ __launch_bounds__(PE_TPB, 8)
void pe_kernel(const float4* __restrict__ X, float4* __restrict__ Out) {
    const int cv   = blockIdx.x * PE_TPB + threadIdx.x;  // column-quad index, 0..1023
    const int row0 = blockIdx.y * PE_ROWS;

    // log2(10000)
    const float L2_10K = 13.287712379549449f;

    float s[4], c[4], sw[4], cw[4];
#pragma unroll
    for (int k = 0; k < 4; k++) {
        const int j = 4 * cv + k;
        // exponent e = (j + (j%2)) / n  -- exact in fp32 (int / 2^12)
        const float e = (float)(j + (j & 1)) * (1.0f / (float)PE_N);
        const float w = exp2f(-e * L2_10K);       // 10000^{-e}
        float ss, cc;
        sincosf((float)row0 * w, &ss, &cc);       // precise: angle can reach 8191
        s[k] = ss; c[k] = cc;
        sincosf(w, &ss, &cc);                     // per-row rotation
        sw[k] = ss; cw[k] = cc;
    }

    const float4* __restrict__ xp = X   + (size_t)row0 * PE_NV4 + cv;
    float4*       __restrict__ yp = Out + (size_t)row0 * PE_NV4 + cv;

#pragma unroll 4
    for (int r = 0; r < PE_ROWS; r++) {
        float4 x = *xp;
        float4 y;
        // columns 4cv+{0,1,2,3} -> parity {even, odd, even, odd} -> {sin, cos, sin, cos}
        y.x = x.x + s[0];
        y.y = x.y + c[1];
        y.z = x.z + s[2];
        y.w = x.w + c[3];
        *yp = y;
        xp += PE_NV4;
        yp += PE_NV4;
#pragma unroll
        for (int k = 0; k < 4; k++) {
            const float ns = fmaf(s[k], cw[k],  c[k] * sw[k]);
            const float nc = fmaf(c[k], cw[k], -s[k] * sw[k]);
            s[k] = ns; c[k] = nc;
        }
    }
}

extern "C" void kernel_launch(void* const* d_in, const int* in_sizes, int n_in,
                              void* d_out, int out_size) {
    (void)in_sizes; (void)n_in; (void)out_size;
    const float4* X   = (const float4*)d_in[0];
    float4*       Out = (float4*)d_out;

    dim3 block(PE_TPB);
    dim3 grid(PE_NV4 / PE_TPB, PE_M / PE_ROWS);   // (4, 256) = 1024 CTAs
    pe_kernel<<<grid, block>>>(X, Out);
}

// round 3
// speedup vs baseline: 1.1223x; 1.0154x over previous
#include <cuda_runtime.h>
#include <cuda_bf16.h>

// PositionalEncoding: out[p][j] = X[p][j] + (j even ? sin(p*w_j) : cos(p*w_j))
//   w_j = 10000^{-(j + (j%2))/n},  n = 4096, m = 8192 rows.
//
// R3: angle-addition recurrence with shared-frequency compression:
//   within a column quad 4cv+{0,1,2,3}, exponents are
//   {4cv, 4cv+2, 4cv+2, 4cv+4}/n -> cols 1 and 2 share w -> only 3 states.
//   ROWS=16, TPB=128, 4096 CTAs (1.73 waves) for near-full occupancy.
//   Streaming loads/stores (no reuse).

#define PE_M     8192
#define PE_N     4096
#define PE_NV4   (PE_N / 4)      // 1024 float4 per row
#define PE_ROWS  16              // rows per thread
#define PE_TPB   128             // threads per block (column-quads)

__global__ __launch_bounds__(PE_TPB, 16)
void pe_kernel(const float4* __restrict__ X, float4* __restrict__ Out) {
    const int cv   = blockIdx.x * PE_TPB + threadIdx.x;  // column-quad index, 0..1023
    const int row0 = blockIdx.y * PE_ROWS;

    const float L2_10K = 13.287712379549449f;  // log2(10000)

    // 3 distinct frequencies per quad: exponents (4cv + 2t)/n, t = 0,1,2
    float s[3], c[3], sw[3], cw[3];
#pragma unroll
    for (int t = 0; t < 3; t++) {
        const float e = (float)(4 * cv + 2 * t) * (1.0f / (float)PE_N);
        const float w = exp2f(-e * L2_10K);           // 10000^{-e}
        sincosf((float)row0 * w, &s[t], &c[t]);       // precise: angle up to ~8191
        __sincosf(w, &sw[t], &cw[t]);                 // fast: w in (1e-4, 1]
    }

    const float4* __restrict__ xp = X   + (size_t)row0 * PE_NV4 + cv;
    float4*       __restrict__ yp = Out + (size_t)row0 * PE_NV4 + cv;

#pragma unroll 4
    for (int r = 0; r < PE_ROWS; r++) {
        float4 x = __ldcs(xp);
        float4 y;
        // cols 4cv+{0,1,2,3}: sin(w0), cos(w1), sin(w1), cos(w2)
        y.x = x.x + s[0];
        y.y = x.y + c[1];
        y.z = x.z + s[1];
        y.w = x.w + c[2];
        __stcs(yp, y);
        xp += PE_NV4;
        yp += PE_NV4;
#pragma unroll
        for (int t = 0; t < 3; t++) {
            const float ns = fmaf(s[t], cw[t],  c[t] * sw[t]);
            const float nc = fmaf(c[t], cw[t], -s[t] * sw[t]);
            s[t] = ns; c[t] = nc;
        }
    }
}

extern "C" void kernel_launch(void* const* d_in, const int* in_sizes, int n_in,
                              void* d_out, int out_size) {
    (void)in_sizes; (void)n_in; (void)out_size;
    const float4* X   = (const float4*)d_in[0];
    float4*       Out = (float4*)d_out;

    dim3 block(PE_TPB);
    dim3 grid(PE_NV4 / PE_TPB, PE_M / PE_ROWS);   // (8, 512) = 4096 CTAs
    pe_kernel<<<grid, block>>>(X, Out);
}